// round 1
// baseline (speedup 1.0000x reference)
#include <cuda_runtime.h>
#include <math.h>
#include <stdint.h>

#define B_ 4
#define C_ 8
#define S_ 512
#define E_ 512
#define H_ 8
#define HD_ 64
#define WINDOW 32

#define NTOK (B_*C_*S_)   /* 16384 tokens */

// Scratch: projected q/k/v and attention context, all [NTOK, E] row-major
// (== [B,C,S,E]); head h lives in columns [h*HD, h*HD+64).
static __device__ float g_q[(size_t)NTOK * E_];
static __device__ float g_k[(size_t)NTOK * E_];
static __device__ float g_v[(size_t)NTOK * E_];
static __device__ float g_ctx[(size_t)NTOK * E_];

// ---------------------------------------------------------------------------
// SGEMM with bias:  out[m,n] = sum_k A[m,k] * W[n,k] + bias[n]
// M = NTOK = 16384, N = K = 512 for all four projections.
// 128x128 block tile, BK=16, 256 threads, 8x8 per-thread microtile.
// ---------------------------------------------------------------------------
#define BM 128
#define BN 128
#define BK 16

__global__ __launch_bounds__(256) void sgemm_bias(
    const float* __restrict__ A, const float* __restrict__ W,
    const float* __restrict__ bias, float* __restrict__ out)
{
    const int K = E_, N = E_;
    __shared__ float As[BK][BM];
    __shared__ float Bs[BK][BN];

    const int tid = threadIdx.x;
    const int m0 = blockIdx.y * BM;
    const int n0 = blockIdx.x * BN;
    const int tx = tid & 15;        // 0..15 -> n microtile
    const int ty = tid >> 4;        // 0..15 -> m microtile

    float acc[8][8];
#pragma unroll
    for (int i = 0; i < 8; i++)
#pragma unroll
        for (int j = 0; j < 8; j++) acc[i][j] = 0.f;

    const int row0 = tid >> 2;          // 0..63
    const int c4   = (tid & 3) * 4;     // 0,4,8,12

    for (int k0 = 0; k0 < K; k0 += BK) {
#pragma unroll
        for (int r = 0; r < 2; r++) {
            const int row = row0 + r * 64;
            float4 av = *(const float4*)(A + (size_t)(m0 + row) * K + k0 + c4);
            As[c4 + 0][row] = av.x; As[c4 + 1][row] = av.y;
            As[c4 + 2][row] = av.z; As[c4 + 3][row] = av.w;
            float4 wv = *(const float4*)(W + (size_t)(n0 + row) * K + k0 + c4);
            Bs[c4 + 0][row] = wv.x; Bs[c4 + 1][row] = wv.y;
            Bs[c4 + 2][row] = wv.z; Bs[c4 + 3][row] = wv.w;
        }
        __syncthreads();

#pragma unroll
        for (int kk = 0; kk < BK; kk++) {
            float a[8], b[8];
#pragma unroll
            for (int i = 0; i < 8; i++) a[i] = As[kk][ty * 8 + i];
#pragma unroll
            for (int j = 0; j < 8; j++) b[j] = Bs[kk][tx * 8 + j];
#pragma unroll
            for (int i = 0; i < 8; i++)
#pragma unroll
                for (int j = 0; j < 8; j++)
                    acc[i][j] += a[i] * b[j];
        }
        __syncthreads();
    }

#pragma unroll
    for (int i = 0; i < 8; i++) {
        float* orow = out + (size_t)(m0 + ty * 8 + i) * N + n0 + tx * 8;
#pragma unroll
        for (int j = 0; j < 8; j++)
            orow[j] = acc[i][j] + bias[n0 + tx * 8 + j];
    }
}

// ---------------------------------------------------------------------------
// Sparse attention.
// One block of 128 threads per (b,c,h,i) query row.
// Allowed columns for row i:  {4t : 4t < L} U [L, i],  L = max(0, i-32).
//   idx < ns (= ceil(L/4))  ->  j = 4*idx        (strided part)
//   idx >= ns               ->  j = L + idx - ns (local window)
// Writes the dense attn row (zeros where masked) and accumulates context.
// ---------------------------------------------------------------------------
__global__ __launch_bounds__(128) void attn_kernel(float* __restrict__ attn_out)
{
    const int i   = blockIdx.x;        // query position
    const int h   = blockIdx.y;        // head
    const int z   = blockIdx.z;        // b*C + c
    const int tid = threadIdx.x;

    __shared__ float qsh[HD_];
    __shared__ float sc[160];          // max nnz = 153
    __shared__ float red[4];
    __shared__ float csum[128];

    const int L   = (i > WINDOW) ? (i - WINDOW) : 0;
    const int ns  = (L + 3) >> 2;
    const int nnz = ns + (i - L + 1);

    const size_t tokBase = ((size_t)z * S_) * E_ + h * HD_;

    if (tid < HD_) qsh[tid] = g_q[tokBase + (size_t)i * E_ + tid];
    __syncthreads();

    // ---- scores -----------------------------------------------------------
    for (int idx = tid; idx < nnz; idx += 128) {
        const int j = (idx < ns) ? (idx << 2) : (L + idx - ns);
        const float* kr = g_k + tokBase + (size_t)j * E_;
        float s = 0.f;
#pragma unroll
        for (int d = 0; d < HD_; d++) s += qsh[d] * kr[d];
        sc[idx] = s * 0.125f;          // 1/sqrt(64)
    }
    __syncthreads();

    // ---- softmax: max -----------------------------------------------------
    float lmax = -1e30f;
    for (int idx = tid; idx < nnz; idx += 128) lmax = fmaxf(lmax, sc[idx]);
#pragma unroll
    for (int off = 16; off; off >>= 1)
        lmax = fmaxf(lmax, __shfl_xor_sync(0xffffffffu, lmax, off));
    if ((tid & 31) == 0) red[tid >> 5] = lmax;
    __syncthreads();
    const float m = fmaxf(fmaxf(red[0], red[1]), fmaxf(red[2], red[3]));

    // ---- softmax: exp + sum ----------------------------------------------
    float lsum = 0.f;
    for (int idx = tid; idx < nnz; idx += 128) {
        const float p = __expf(sc[idx] - m);
        sc[idx] = p;
        lsum += p;
    }
#pragma unroll
    for (int off = 16; off; off >>= 1)
        lsum += __shfl_xor_sync(0xffffffffu, lsum, off);
    __syncthreads();                   // everyone has read red[] for m
    if ((tid & 31) == 0) red[tid >> 5] = lsum;
    __syncthreads();
    const float inv = 1.f / (red[0] + red[1] + red[2] + red[3]);

    for (int idx = tid; idx < nnz; idx += 128) sc[idx] *= inv;
    __syncthreads();

    // ---- dense attn row write (layout [B,H,C,S,S]) ------------------------
    const int b = z / C_, c = z % C_;
    float* arow = attn_out +
        ((((size_t)(b * H_ + h) * C_ + c) * S_ + i) * (size_t)S_);
    for (int j = tid; j < S_; j += 128) {
        float val = 0.f;
        if (j <= i) {
            if (j >= L)            val = sc[ns + j - L];
            else if ((j & 3) == 0) val = sc[j >> 2];
        }
        arow[j] = val;
    }

    // ---- context: ctx[d] = sum_idx p[idx] * v[j_idx][d] -------------------
    const int g = tid >> 6;            // 0 or 1: split nnz between two halves
    const int d = tid & 63;
    float acc = 0.f;
    for (int idx = g; idx < nnz; idx += 2) {
        const int j = (idx < ns) ? (idx << 2) : (L + idx - ns);
        acc += sc[idx] * g_v[tokBase + (size_t)j * E_ + d];
    }
    csum[tid] = acc;
    __syncthreads();
    if (tid < 64)
        g_ctx[tokBase + (size_t)i * E_ + tid] = csum[tid] + csum[tid + 64];
}

// ---------------------------------------------------------------------------
extern "C" void kernel_launch(void* const* d_in, const int* in_sizes, int n_in,
                              void* d_out, int out_size)
{
    const float* query = (const float*)d_in[0];
    const float* key_  = (const float*)d_in[1];
    const float* value = (const float*)d_in[2];
    const float* Wq = (const float*)d_in[3];
    const float* bq = (const float*)d_in[4];
    const float* Wk = (const float*)d_in[5];
    const float* bk = (const float*)d_in[6];
    const float* Wv = (const float*)d_in[7];
    const float* bv = (const float*)d_in[8];
    const float* Wo = (const float*)d_in[9];
    const float* bo = (const float*)d_in[10];

    float* out  = (float*)d_out;                       // [B,C,S,E]
    float* attn = out + (size_t)NTOK * E_;             // [B,H,C,S,S]

    float *q_, *k_, *v_, *ctx_;
    cudaGetSymbolAddress((void**)&q_,   g_q);
    cudaGetSymbolAddress((void**)&k_,   g_k);
    cudaGetSymbolAddress((void**)&v_,   g_v);
    cudaGetSymbolAddress((void**)&ctx_, g_ctx);

    dim3 ggrid(E_ / BN, NTOK / BM);    // (4, 128)
    sgemm_bias<<<ggrid, 256>>>(query, Wq, bq, q_);
    sgemm_bias<<<ggrid, 256>>>(key_,  Wk, bk, k_);
    sgemm_bias<<<ggrid, 256>>>(value, Wv, bv, v_);

    dim3 agrid(S_, H_, B_ * C_);       // 512 x 8 x 32 blocks
    attn_kernel<<<agrid, 128>>>(attn);

    sgemm_bias<<<ggrid, 256>>>(ctx_, Wo, bo, out);
}

// round 3
// speedup vs baseline: 2.9795x; 2.9795x over previous
#include <cuda_runtime.h>
#include <math.h>
#include <stdint.h>

#define B_ 4
#define C_ 8
#define S_ 512
#define E_ 512
#define H_ 8
#define HD_ 64
#define WINDOW 32

#define NTOK (B_*C_*S_)   /* 16384 tokens */

static __device__ float g_q[(size_t)NTOK * E_];
static __device__ float g_k[(size_t)NTOK * E_];
static __device__ float g_v[(size_t)NTOK * E_];
static __device__ float g_ctx[(size_t)NTOK * E_];

// ---------------------------------------------------------------------------
// SGEMM with bias:  out[m,n] = sum_k A[m,k] * W[n,k] + bias[n]
// ---------------------------------------------------------------------------
#define BM 128
#define BN 128
#define BK 16

__global__ __launch_bounds__(256) void sgemm_bias(
    const float* __restrict__ A, const float* __restrict__ W,
    const float* __restrict__ bias, float* __restrict__ out)
{
    const int K = E_, N = E_;
    __shared__ float As[BK][BM];
    __shared__ float Bs[BK][BN];

    const int tid = threadIdx.x;
    const int m0 = blockIdx.y * BM;
    const int n0 = blockIdx.x * BN;
    const int tx = tid & 15;
    const int ty = tid >> 4;

    float acc[8][8];
#pragma unroll
    for (int i = 0; i < 8; i++)
#pragma unroll
        for (int j = 0; j < 8; j++) acc[i][j] = 0.f;

    const int row0 = tid >> 2;
    const int c4   = (tid & 3) * 4;

    for (int k0 = 0; k0 < K; k0 += BK) {
#pragma unroll
        for (int r = 0; r < 2; r++) {
            const int row = row0 + r * 64;
            float4 av = *(const float4*)(A + (size_t)(m0 + row) * K + k0 + c4);
            As[c4 + 0][row] = av.x; As[c4 + 1][row] = av.y;
            As[c4 + 2][row] = av.z; As[c4 + 3][row] = av.w;
            float4 wv = *(const float4*)(W + (size_t)(n0 + row) * K + k0 + c4);
            Bs[c4 + 0][row] = wv.x; Bs[c4 + 1][row] = wv.y;
            Bs[c4 + 2][row] = wv.z; Bs[c4 + 3][row] = wv.w;
        }
        __syncthreads();

#pragma unroll
        for (int kk = 0; kk < BK; kk++) {
            float a[8], b[8];
#pragma unroll
            for (int i = 0; i < 8; i++) a[i] = As[kk][ty * 8 + i];
#pragma unroll
            for (int j = 0; j < 8; j++) b[j] = Bs[kk][tx * 8 + j];
#pragma unroll
            for (int i = 0; i < 8; i++)
#pragma unroll
                for (int j = 0; j < 8; j++)
                    acc[i][j] += a[i] * b[j];
        }
        __syncthreads();
    }

#pragma unroll
    for (int i = 0; i < 8; i++) {
        float* orow = out + (size_t)(m0 + ty * 8 + i) * N + n0 + tx * 8;
#pragma unroll
        for (int j = 0; j < 8; j++)
            orow[j] = acc[i][j] + bias[n0 + tx * 8 + j];
    }
}

// ---------------------------------------------------------------------------
// Tiled sparse attention.
// One block of 256 threads per (z, h, 64-query tile).
// Column union for tile [q0, q0+64):
//   u < Ncs           -> j = 4u               (strided, j < wstart)
//   u >= Ncs          -> j = wstart + u - Ncs (window span [wstart, we])
// wstart = max(0, q0-32), we = q0+63, Ncs = wstart/4, NU <= 200.
// ---------------------------------------------------------------------------
#define QT 64
#define KLD 65
#define SCLD 209

__global__ __launch_bounds__(256) void attn_tiled(float* __restrict__ attn_out)
{
    extern __shared__ float smem[];
    float* Qs = smem;                  // [64][KLD]
    float* Ks = Qs + QT * KLD;         // [64][KLD]  (reused for V)
    float* sc = Ks + QT * KLD;         // [64][SCLD]

    const int tid = threadIdx.x;
    const int qt  = blockIdx.x;
    const int h   = blockIdx.y;
    const int z   = blockIdx.z;

    const int q0     = qt * QT;
    const int we     = q0 + QT - 1;
    const int wstart = (q0 >= WINDOW) ? (q0 - WINDOW) : 0;
    const int Ncs    = wstart >> 2;
    const int NU     = Ncs + (we - wstart + 1);
    const int nch    = (NU + 63) >> 6;

    const size_t tokBase = ((size_t)z * S_) * E_ + h * HD_;

    const int tx = tid & 15;
    const int ty = tid >> 4;

    // ---- load Q tile -------------------------------------------------------
    for (int t = tid; t < QT * 16; t += 256) {
        const int r = t >> 4, c = (t & 15) << 2;
        float4 v = *(const float4*)(g_q + tokBase + (size_t)(q0 + r) * E_ + c);
        float* d = Qs + r * KLD + c;
        d[0] = v.x; d[1] = v.y; d[2] = v.z; d[3] = v.w;
    }

    // ---- scores over column chunks ----------------------------------------
    for (int ch = 0; ch < nch; ch++) {
        const int uc0 = ch << 6;
        __syncthreads();
        for (int t = tid; t < QT * 16; t += 256) {
            const int r = t >> 4, c = (t & 15) << 2;
            const int u = uc0 + r;
            float4 v = make_float4(0.f, 0.f, 0.f, 0.f);
            if (u < NU) {
                const int j = (u < Ncs) ? (u << 2) : (wstart + u - Ncs);
                v = *(const float4*)(g_k + tokBase + (size_t)j * E_ + c);
            }
            float* d = Ks + r * KLD + c;
            d[0] = v.x; d[1] = v.y; d[2] = v.z; d[3] = v.w;
        }
        __syncthreads();

        float s[4][4];
#pragma unroll
        for (int a = 0; a < 4; a++)
#pragma unroll
            for (int b = 0; b < 4; b++) s[a][b] = 0.f;

#pragma unroll 8
        for (int d = 0; d < HD_; d++) {
            float a[4], b[4];
#pragma unroll
            for (int ii = 0; ii < 4; ii++) a[ii] = Qs[(ty * 4 + ii) * KLD + d];
#pragma unroll
            for (int jj = 0; jj < 4; jj++) b[jj] = Ks[(tx * 4 + jj) * KLD + d];
#pragma unroll
            for (int ii = 0; ii < 4; ii++)
#pragma unroll
                for (int jj = 0; jj < 4; jj++) s[ii][jj] += a[ii] * b[jj];
        }

        const float NEGINF = __int_as_float(0xff800000);
#pragma unroll
        for (int ii = 0; ii < 4; ii++) {
            const int i = q0 + ty * 4 + ii;
#pragma unroll
            for (int jj = 0; jj < 4; jj++) {
                const int u = uc0 + tx * 4 + jj;
                if (u < NU) {
                    const int j = (u < Ncs) ? (u << 2) : (wstart + u - Ncs);
                    const bool ok = (j <= i) && ((j >= i - WINDOW) || ((j & 3) == 0));
                    sc[(ty * 4 + ii) * SCLD + u] = ok ? s[ii][jj] * 0.125f : NEGINF;
                }
            }
        }
    }
    __syncthreads();

    // ---- softmax: 4 threads per row ---------------------------------------
    {
        const int row  = tid >> 2;
        const int lane = tid & 3;
        float* srow = sc + row * SCLD;
        float m = __int_as_float(0xff800000);
        for (int u = lane; u < NU; u += 4) m = fmaxf(m, srow[u]);
        m = fmaxf(m, __shfl_xor_sync(0xffffffffu, m, 1));
        m = fmaxf(m, __shfl_xor_sync(0xffffffffu, m, 2));
        float sum = 0.f;
        for (int u = lane; u < NU; u += 4) {
            const float p = __expf(srow[u] - m);
            srow[u] = p;
            sum += p;
        }
        sum += __shfl_xor_sync(0xffffffffu, sum, 1);
        sum += __shfl_xor_sync(0xffffffffu, sum, 2);
        const float inv = 1.f / sum;
        for (int u = lane; u < NU; u += 4) srow[u] *= inv;
    }
    __syncthreads();

    // ---- dense attn write ([B,H,C,S,S]) -----------------------------------
    // Value rule per column j:
    //   wstart <= j <= we        -> srow[Ncs + j - wstart]  (0 if masked)
    //   j < wstart && j%4 == 0   -> srow[j/4]
    //   otherwise                -> 0
    {
        const int b = z / C_, c = z % C_;
        float* abase = attn_out +
            ((((size_t)(b * H_ + h) * C_ + c) * S_ + q0) * (size_t)S_);
        for (int t = tid; t < QT * (S_ / 4); t += 256) {
            const int r  = t >> 7;
            const int j0 = (t & 127) << 2;
            const float* srow = sc + r * SCLD;
            float4 v;
            if (j0 >= wstart && j0 + 3 <= we) {
                const int u = Ncs + j0 - wstart;
                v = make_float4(srow[u], srow[u + 1], srow[u + 2], srow[u + 3]);
            } else {
                float vv[4];
#pragma unroll
                for (int t4 = 0; t4 < 4; t4++) {
                    const int j = j0 + t4;
                    float val = 0.f;
                    if (j >= wstart && j <= we)      val = srow[Ncs + j - wstart];
                    else if (j < wstart && t4 == 0)  val = srow[j >> 2];
                    vv[t4] = val;
                }
                v = make_float4(vv[0], vv[1], vv[2], vv[3]);
            }
            *(float4*)(abase + (size_t)r * S_ + j0) = v;
        }
    }

    // ---- context: ctx = P(64 x NU) * V_U(NU x 64) -------------------------
    float acc[4][4];
#pragma unroll
    for (int a = 0; a < 4; a++)
#pragma unroll
        for (int b = 0; b < 4; b++) acc[a][b] = 0.f;

    for (int ch = 0; ch < nch; ch++) {
        const int uc0 = ch << 6;
        __syncthreads();
        for (int t = tid; t < QT * 16; t += 256) {
            const int r = t >> 4, c = (t & 15) << 2;
            const int u = uc0 + r;
            float4 v = make_float4(0.f, 0.f, 0.f, 0.f);
            if (u < NU) {
                const int j = (u < Ncs) ? (u << 2) : (wstart + u - Ncs);
                v = *(const float4*)(g_v + tokBase + (size_t)j * E_ + c);
            }
            float* d = Ks + r * KLD + c;
            d[0] = v.x; d[1] = v.y; d[2] = v.z; d[3] = v.w;
        }
        __syncthreads();

        const int rem = NU - uc0;
        const int lim = rem < 64 ? rem : 64;
        for (int ul = 0; ul < lim; ul++) {
            float a[4], b[4];
#pragma unroll
            for (int jj = 0; jj < 4; jj++) b[jj] = Ks[ul * KLD + tx * 4 + jj];
#pragma unroll
            for (int ii = 0; ii < 4; ii++) a[ii] = sc[(ty * 4 + ii) * SCLD + uc0 + ul];
#pragma unroll
            for (int ii = 0; ii < 4; ii++)
#pragma unroll
                for (int jj = 0; jj < 4; jj++) acc[ii][jj] += a[ii] * b[jj];
        }
    }

#pragma unroll
    for (int ii = 0; ii < 4; ii++) {
        const int i = q0 + ty * 4 + ii;
        float* crow = g_ctx + tokBase + (size_t)i * E_;
#pragma unroll
        for (int jj = 0; jj < 4; jj++) crow[tx * 4 + jj] = acc[ii][jj];
    }
}

// ---------------------------------------------------------------------------
extern "C" void kernel_launch(void* const* d_in, const int* in_sizes, int n_in,
                              void* d_out, int out_size)
{
    const float* query = (const float*)d_in[0];
    const float* key_  = (const float*)d_in[1];
    const float* value = (const float*)d_in[2];
    const float* Wq = (const float*)d_in[3];
    const float* bq = (const float*)d_in[4];
    const float* Wk = (const float*)d_in[5];
    const float* bk = (const float*)d_in[6];
    const float* Wv = (const float*)d_in[7];
    const float* bv = (const float*)d_in[8];
    const float* Wo = (const float*)d_in[9];
    const float* bo = (const float*)d_in[10];

    float* out  = (float*)d_out;                       // [B,C,S,E]
    float* attn = out + (size_t)NTOK * E_;             // [B,H,C,S,S]

    float *q_, *k_, *v_, *ctx_;
    cudaGetSymbolAddress((void**)&q_,   g_q);
    cudaGetSymbolAddress((void**)&k_,   g_k);
    cudaGetSymbolAddress((void**)&v_,   g_v);
    cudaGetSymbolAddress((void**)&ctx_, g_ctx);

    const int ATTN_SMEM = (2 * QT * KLD + QT * SCLD) * (int)sizeof(float);
    cudaFuncSetAttribute(attn_tiled,
        cudaFuncAttributeMaxDynamicSharedMemorySize, ATTN_SMEM);

    dim3 ggrid(E_ / BN, NTOK / BM);    // (4, 128)
    sgemm_bias<<<ggrid, 256>>>(query, Wq, bq, q_);
    sgemm_bias<<<ggrid, 256>>>(key_,  Wk, bk, k_);
    sgemm_bias<<<ggrid, 256>>>(value, Wv, bv, v_);

    dim3 agrid(S_ / QT, H_, B_ * C_);  // (8, 8, 32)
    attn_tiled<<<agrid, 256, ATTN_SMEM>>>(attn);

    sgemm_bias<<<ggrid, 256>>>(ctx_, Wo, bo, out);
}

// round 5
// speedup vs baseline: 5.7701x; 1.9366x over previous
#include <cuda_runtime.h>
#include <cuda_bf16.h>
#include <math.h>
#include <stdint.h>

#define B_ 4
#define C_ 8
#define S_ 512
#define E_ 512
#define H_ 8
#define HD_ 64
#define WINDOW 32
#define NTOK (B_*C_*S_)   /* 16384 */

static __device__ float g_q[(size_t)NTOK * E_];
static __device__ float g_k[(size_t)NTOK * E_];
static __device__ float g_v[(size_t)NTOK * E_];
static __device__ float g_ctx[(size_t)NTOK * E_];

static __device__ __nv_bfloat16 g_Ah[(size_t)NTOK * E_];
static __device__ __nv_bfloat16 g_Al[(size_t)NTOK * E_];
static __device__ __nv_bfloat16 g_Wh[(size_t)E_ * E_];
static __device__ __nv_bfloat16 g_Wl[(size_t)E_ * E_];

// ============================ helpers ======================================
__device__ __forceinline__ uint32_t smem_to_u32(const void* p) {
    uint32_t a;
    asm("{ .reg .u64 t; cvta.to.shared.u64 t, %1; cvt.u32.u64 %0, t; }"
        : "=r"(a) : "l"(p));
    return a;
}
__device__ __forceinline__ void cp16(uint32_t dst, const void* src) {
    asm volatile("cp.async.cg.shared.global [%0], [%1], 16;"
                 :: "r"(dst), "l"(src) : "memory");
}
__device__ __forceinline__ void ldsm4(uint32_t* r, uint32_t addr) {
    asm volatile("ldmatrix.sync.aligned.m8n8.x4.shared.b16 {%0,%1,%2,%3}, [%4];"
                 : "=r"(r[0]), "=r"(r[1]), "=r"(r[2]), "=r"(r[3]) : "r"(addr));
}
__device__ __forceinline__ void mma16816(float* d, const uint32_t* a,
                                         uint32_t b0, uint32_t b1) {
    asm volatile("mma.sync.aligned.m16n8k16.row.col.f32.bf16.bf16.f32 "
                 "{%0,%1,%2,%3}, {%4,%5,%6,%7}, {%8,%9}, {%0,%1,%2,%3};"
                 : "+f"(d[0]), "+f"(d[1]), "+f"(d[2]), "+f"(d[3])
                 : "r"(a[0]), "r"(a[1]), "r"(a[2]), "r"(a[3]), "r"(b0), "r"(b1));
}
// 128 rows x 32 bf16 (64 B/row); physical 16B-chunk = c ^ ((row>>1)&3):
// conflict-free ldmatrix (8 rows hit all 32 banks).
__device__ __forceinline__ uint32_t swz(int row, int c) {
    return (uint32_t)(row * 64 + ((c ^ ((row >> 1) & 3)) << 4));
}

// ============================ split kernel =================================
__global__ __launch_bounds__(256) void split_bf16(
    const float4* __restrict__ src, uint2* __restrict__ hi, uint2* __restrict__ lo)
{
    const int i = blockIdx.x * 256 + threadIdx.x;
    float4 v = src[i];
    __nv_bfloat16 h0 = __float2bfloat16(v.x);
    __nv_bfloat16 h1 = __float2bfloat16(v.y);
    __nv_bfloat16 h2 = __float2bfloat16(v.z);
    __nv_bfloat16 h3 = __float2bfloat16(v.w);
    __nv_bfloat16 l0 = __float2bfloat16(v.x - __bfloat162float(h0));
    __nv_bfloat16 l1 = __float2bfloat16(v.y - __bfloat162float(h1));
    __nv_bfloat16 l2 = __float2bfloat16(v.z - __bfloat162float(h2));
    __nv_bfloat16 l3 = __float2bfloat16(v.w - __bfloat162float(h3));
    uint2 ph, pl;
    ph.x = (uint32_t)__bfloat16_as_ushort(h0) | ((uint32_t)__bfloat16_as_ushort(h1) << 16);
    ph.y = (uint32_t)__bfloat16_as_ushort(h2) | ((uint32_t)__bfloat16_as_ushort(h3) << 16);
    pl.x = (uint32_t)__bfloat16_as_ushort(l0) | ((uint32_t)__bfloat16_as_ushort(l1) << 16);
    pl.y = (uint32_t)__bfloat16_as_ushort(l2) | ((uint32_t)__bfloat16_as_ushort(l3) << 16);
    hi[i] = ph; lo[i] = pl;
}

// ============================ HMMA GEMM ====================================
// out[m,n] = sum_k A[m,k]*W[n,k] + bias[n]  via bf16x3 (hh + hl + lh).
// CTA 128x128, 8 warps (2 M x 4 N), warp tile 64x32.
// K: 16 double-buffered stages of 32 (cp.async).
#define GM 128
#define GN 128
#define KCH 32
#define NST (E_/KCH)             /* 16 */
#define TILE_B (128*64)          /* 8192 B per bf16 tile  */
#define STAGE_B (4*TILE_B)       /* Ah|Al|Wh|Wl = 32768 B */
#define GSMEM (2*STAGE_B)        /* 65536 B               */

__device__ __forceinline__ void gemm_issue_stage(
    uint32_t sb, int s, int m0, int n0, int tid,
    const __nv_bfloat16* Ah, const __nv_bfloat16* Al,
    const __nv_bfloat16* Wh, const __nv_bfloat16* Wl)
{
    const uint32_t base = sb + (uint32_t)(s & 1) * STAGE_B;
    const int k0 = s * KCH;
#pragma unroll
    for (int q = 0; q < 2; q++) {
        const int id  = tid * 2 + q;      // 0..511
        const int row = id >> 2;
        const int c   = id & 3;
        const uint32_t d = base + swz(row, c);
        const size_t ga = (size_t)(m0 + row) * E_ + k0 + c * 8;
        const size_t gw = (size_t)(n0 + row) * E_ + k0 + c * 8;
        cp16(d,              Ah + ga);
        cp16(d + TILE_B,     Al + ga);
        cp16(d + 2 * TILE_B, Wh + gw);
        cp16(d + 3 * TILE_B, Wl + gw);
    }
    asm volatile("cp.async.commit_group;" ::: "memory");
}

__global__ __launch_bounds__(256) void gemm_mma(
    const __nv_bfloat16* __restrict__ Ah, const __nv_bfloat16* __restrict__ Al,
    const __nv_bfloat16* __restrict__ Wh, const __nv_bfloat16* __restrict__ Wl,
    const float* __restrict__ bias, float* __restrict__ out)
{
    extern __shared__ char gsm[];
    const uint32_t sb = smem_to_u32(gsm);
    const int tid  = threadIdx.x;
    const int lane = tid & 31;
    const int wid  = tid >> 5;
    const int wm   = wid & 1;          // 0..1
    const int wn   = wid >> 1;         // 0..3
    const int m0 = blockIdx.x * GM;
    const int n0 = blockIdx.y * GN;

    float acc[4][4][4];
#pragma unroll
    for (int a = 0; a < 4; a++)
#pragma unroll
        for (int b = 0; b < 4; b++)
#pragma unroll
            for (int c = 0; c < 4; c++) acc[a][b][c] = 0.f;

    gemm_issue_stage(sb, 0, m0, n0, tid, Ah, Al, Wh, Wl);
    gemm_issue_stage(sb, 1, m0, n0, tid, Ah, Al, Wh, Wl);

    for (int s = 0; s < NST; s++) {
        if (s < NST - 1) asm volatile("cp.async.wait_group 1;" ::: "memory");
        else             asm volatile("cp.async.wait_group 0;" ::: "memory");
        __syncthreads();

        const uint32_t aB = sb + (uint32_t)(s & 1) * STAGE_B;
        const uint32_t wB = aB + 2 * TILE_B;

#pragma unroll
        for (int ks = 0; ks < 2; ks++) {
            uint32_t af[4][4], whf[2][4], wlf[2][4];
            // A hi fragments: one x4 per m16 tile
#pragma unroll
            for (int mt = 0; mt < 4; mt++) {
                const int row = wm * 64 + mt * 16 + (lane & 15);
                const int c   = ks * 2 + (lane >> 4);
                ldsm4(af[mt], aB + swz(row, c));
            }
            // W hi/lo fragments: one x4 per pair of n8 tiles
#pragma unroll
            for (int np = 0; np < 2; np++) {
                const int row = wn * 32 + np * 16 + (lane & 7) + ((lane >> 4) & 1) * 8;
                const int c   = ks * 2 + ((lane >> 3) & 1);
                const uint32_t addr = wB + swz(row, c);
                ldsm4(whf[np], addr);
                ldsm4(wlf[np], addr + TILE_B);
            }
            // hi*hi and hi*lo
#pragma unroll
            for (int mt = 0; mt < 4; mt++)
#pragma unroll
                for (int nt = 0; nt < 4; nt++) {
                    const int np = nt >> 1, o = (nt & 1) * 2;
                    mma16816(acc[mt][nt], af[mt], whf[np][o], whf[np][o + 1]);
                    mma16816(acc[mt][nt], af[mt], wlf[np][o], wlf[np][o + 1]);
                }
            // reload A lo into the same registers, then lo*hi
#pragma unroll
            for (int mt = 0; mt < 4; mt++) {
                const int row = wm * 64 + mt * 16 + (lane & 15);
                const int c   = ks * 2 + (lane >> 4);
                ldsm4(af[mt], aB + TILE_B + swz(row, c));
            }
#pragma unroll
            for (int mt = 0; mt < 4; mt++)
#pragma unroll
                for (int nt = 0; nt < 4; nt++) {
                    const int np = nt >> 1, o = (nt & 1) * 2;
                    mma16816(acc[mt][nt], af[mt], whf[np][o], whf[np][o + 1]);
                }
        }
        __syncthreads();
        if (s + 2 < NST)
            gemm_issue_stage(sb, s + 2, m0, n0, tid, Ah, Al, Wh, Wl);
    }

    // ---- epilogue: bias + store ------------------------------------------
#pragma unroll
    for (int nt = 0; nt < 4; nt++) {
        const int gn = n0 + wn * 32 + nt * 8 + (lane & 3) * 2;
        const float2 bv = *(const float2*)(bias + gn);
#pragma unroll
        for (int mt = 0; mt < 4; mt++) {
            const int gm = m0 + wm * 64 + mt * 16 + (lane >> 2);
            float2 v0, v1;
            v0.x = acc[mt][nt][0] + bv.x; v0.y = acc[mt][nt][1] + bv.y;
            v1.x = acc[mt][nt][2] + bv.x; v1.y = acc[mt][nt][3] + bv.y;
            *(float2*)(out + (size_t)gm * E_ + gn)       = v0;
            *(float2*)(out + (size_t)(gm + 8) * E_ + gn) = v1;
        }
    }
}

// ============================ sparse attention =============================
#define QT 64
#define KLD 65
#define SCLD 209

__global__ __launch_bounds__(256) void attn_tiled(float* __restrict__ attn_out)
{
    extern __shared__ float fsmem[];
    float* Qs = fsmem;
    float* Ks = Qs + QT * KLD;
    float* sc = Ks + QT * KLD;

    const int tid = threadIdx.x;
    const int qt  = blockIdx.x;
    const int h   = blockIdx.y;
    const int z   = blockIdx.z;

    const int q0     = qt * QT;
    const int we     = q0 + QT - 1;
    const int wstart = (q0 >= WINDOW) ? (q0 - WINDOW) : 0;
    const int Ncs    = wstart >> 2;
    const int NU     = Ncs + (we - wstart + 1);
    const int nch    = (NU + 63) >> 6;

    const size_t tokBase = ((size_t)z * S_) * E_ + h * HD_;
    const int tx = tid & 15;
    const int ty = tid >> 4;

    for (int t = tid; t < QT * 16; t += 256) {
        const int r = t >> 4, c = (t & 15) << 2;
        float4 v = *(const float4*)(g_q + tokBase + (size_t)(q0 + r) * E_ + c);
        float* d = Qs + r * KLD + c;
        d[0] = v.x; d[1] = v.y; d[2] = v.z; d[3] = v.w;
    }

    for (int ch = 0; ch < nch; ch++) {
        const int uc0 = ch << 6;
        __syncthreads();
        for (int t = tid; t < QT * 16; t += 256) {
            const int r = t >> 4, c = (t & 15) << 2;
            const int u = uc0 + r;
            float4 v = make_float4(0.f, 0.f, 0.f, 0.f);
            if (u < NU) {
                const int j = (u < Ncs) ? (u << 2) : (wstart + u - Ncs);
                v = *(const float4*)(g_k + tokBase + (size_t)j * E_ + c);
            }
            float* d = Ks + r * KLD + c;
            d[0] = v.x; d[1] = v.y; d[2] = v.z; d[3] = v.w;
        }
        __syncthreads();

        float s[4][4];
#pragma unroll
        for (int a = 0; a < 4; a++)
#pragma unroll
            for (int b = 0; b < 4; b++) s[a][b] = 0.f;

#pragma unroll 8
        for (int d = 0; d < HD_; d++) {
            float a[4], b[4];
#pragma unroll
            for (int ii = 0; ii < 4; ii++) a[ii] = Qs[(ty * 4 + ii) * KLD + d];
#pragma unroll
            for (int jj = 0; jj < 4; jj++) b[jj] = Ks[(tx * 4 + jj) * KLD + d];
#pragma unroll
            for (int ii = 0; ii < 4; ii++)
#pragma unroll
                for (int jj = 0; jj < 4; jj++) s[ii][jj] += a[ii] * b[jj];
        }

        const float NEGINF = __int_as_float(0xff800000);
#pragma unroll
        for (int ii = 0; ii < 4; ii++) {
            const int i = q0 + ty * 4 + ii;
#pragma unroll
            for (int jj = 0; jj < 4; jj++) {
                const int u = uc0 + tx * 4 + jj;
                if (u < NU) {
                    const int j = (u < Ncs) ? (u << 2) : (wstart + u - Ncs);
                    const bool ok = (j <= i) && ((j >= i - WINDOW) || ((j & 3) == 0));
                    sc[(ty * 4 + ii) * SCLD + u] = ok ? s[ii][jj] * 0.125f : NEGINF;
                }
            }
        }
    }
    __syncthreads();

    {
        const int row  = tid >> 2;
        const int lane = tid & 3;
        float* srow = sc + row * SCLD;
        float m = __int_as_float(0xff800000);
        for (int u = lane; u < NU; u += 4) m = fmaxf(m, srow[u]);
        m = fmaxf(m, __shfl_xor_sync(0xffffffffu, m, 1));
        m = fmaxf(m, __shfl_xor_sync(0xffffffffu, m, 2));
        float sum = 0.f;
        for (int u = lane; u < NU; u += 4) {
            const float p = __expf(srow[u] - m);
            srow[u] = p;
            sum += p;
        }
        sum += __shfl_xor_sync(0xffffffffu, sum, 1);
        sum += __shfl_xor_sync(0xffffffffu, sum, 2);
        const float inv = 1.f / sum;
        for (int u = lane; u < NU; u += 4) srow[u] *= inv;
    }
    __syncthreads();

    {
        const int b = z / C_, c = z % C_;
        float* abase = attn_out +
            ((((size_t)(b * H_ + h) * C_ + c) * S_ + q0) * (size_t)S_);
        for (int t = tid; t < QT * (S_ / 4); t += 256) {
            const int r  = t >> 7;
            const int j0 = (t & 127) << 2;
            const float* srow = sc + r * SCLD;
            float4 v;
            if (j0 >= wstart && j0 + 3 <= we) {
                const int u = Ncs + j0 - wstart;
                v = make_float4(srow[u], srow[u + 1], srow[u + 2], srow[u + 3]);
            } else {
                float vv[4];
#pragma unroll
                for (int t4 = 0; t4 < 4; t4++) {
                    const int j = j0 + t4;
                    float val = 0.f;
                    if (j >= wstart && j <= we)      val = srow[Ncs + j - wstart];
                    else if (j < wstart && t4 == 0)  val = srow[j >> 2];
                    vv[t4] = val;
                }
                v = make_float4(vv[0], vv[1], vv[2], vv[3]);
            }
            *(float4*)(abase + (size_t)r * S_ + j0) = v;
        }
    }

    float acc[4][4];
#pragma unroll
    for (int a = 0; a < 4; a++)
#pragma unroll
        for (int b = 0; b < 4; b++) acc[a][b] = 0.f;

    for (int ch = 0; ch < nch; ch++) {
        const int uc0 = ch << 6;
        __syncthreads();
        for (int t = tid; t < QT * 16; t += 256) {
            const int r = t >> 4, c = (t & 15) << 2;
            const int u = uc0 + r;
            float4 v = make_float4(0.f, 0.f, 0.f, 0.f);
            if (u < NU) {
                const int j = (u < Ncs) ? (u << 2) : (wstart + u - Ncs);
                v = *(const float4*)(g_v + tokBase + (size_t)j * E_ + c);
            }
            float* d = Ks + r * KLD + c;
            d[0] = v.x; d[1] = v.y; d[2] = v.z; d[3] = v.w;
        }
        __syncthreads();

        const int rem = NU - uc0;
        const int lim = rem < 64 ? rem : 64;
        for (int ul = 0; ul < lim; ul++) {
            float a[4], b[4];
#pragma unroll
            for (int jj = 0; jj < 4; jj++) b[jj] = Ks[ul * KLD + tx * 4 + jj];
#pragma unroll
            for (int ii = 0; ii < 4; ii++) a[ii] = sc[(ty * 4 + ii) * SCLD + uc0 + ul];
#pragma unroll
            for (int ii = 0; ii < 4; ii++)
#pragma unroll
                for (int jj = 0; jj < 4; jj++) acc[ii][jj] += a[ii] * b[jj];
        }
    }

#pragma unroll
    for (int ii = 0; ii < 4; ii++) {
        const int i = q0 + ty * 4 + ii;
        float* crow = g_ctx + tokBase + (size_t)i * E_;
#pragma unroll
        for (int jj = 0; jj < 4; jj++) crow[tx * 4 + jj] = acc[ii][jj];
    }
}

// ===========================================================================
extern "C" void kernel_launch(void* const* d_in, const int* in_sizes, int n_in,
                              void* d_out, int out_size)
{
    const float* query = (const float*)d_in[0];
    const float* key_  = (const float*)d_in[1];
    const float* value = (const float*)d_in[2];
    const float* Wq = (const float*)d_in[3];
    const float* bq = (const float*)d_in[4];
    const float* Wk = (const float*)d_in[5];
    const float* bk = (const float*)d_in[6];
    const float* Wv = (const float*)d_in[7];
    const float* bv = (const float*)d_in[8];
    const float* Wo = (const float*)d_in[9];
    const float* bo = (const float*)d_in[10];

    float* out  = (float*)d_out;
    float* attn = out + (size_t)NTOK * E_;

    float *q_, *k_, *v_, *ctx_;
    __nv_bfloat16 *Ah, *Al, *Wh, *Wl;
    cudaGetSymbolAddress((void**)&q_,   g_q);
    cudaGetSymbolAddress((void**)&k_,   g_k);
    cudaGetSymbolAddress((void**)&v_,   g_v);
    cudaGetSymbolAddress((void**)&ctx_, g_ctx);
    cudaGetSymbolAddress((void**)&Ah,   g_Ah);
    cudaGetSymbolAddress((void**)&Al,   g_Al);
    cudaGetSymbolAddress((void**)&Wh,   g_Wh);
    cudaGetSymbolAddress((void**)&Wl,   g_Wl);

    const int ATTN_SMEM = (2 * QT * KLD + QT * SCLD) * (int)sizeof(float);
    cudaFuncSetAttribute(attn_tiled,
        cudaFuncAttributeMaxDynamicSharedMemorySize, ATTN_SMEM);
    cudaFuncSetAttribute(gemm_mma,
        cudaFuncAttributeMaxDynamicSharedMemorySize, GSMEM);

    const int NA4 = NTOK * E_ / 4;
    const int NW4 = E_ * E_ / 4;
    dim3 mgrid(NTOK / GM, E_ / GN);      // (128, 4)

    // Q projection
    split_bf16<<<NA4 / 256, 256>>>((const float4*)query, (uint2*)Ah, (uint2*)Al);
    split_bf16<<<NW4 / 256, 256>>>((const float4*)Wq, (uint2*)Wh, (uint2*)Wl);
    gemm_mma<<<mgrid, 256, GSMEM>>>(Ah, Al, Wh, Wl, bq, q_);
    // K projection
    split_bf16<<<NA4 / 256, 256>>>((const float4*)key_, (uint2*)Ah, (uint2*)Al);
    split_bf16<<<NW4 / 256, 256>>>((const float4*)Wk, (uint2*)Wh, (uint2*)Wl);
    gemm_mma<<<mgrid, 256, GSMEM>>>(Ah, Al, Wh, Wl, bk, k_);
    // V projection
    split_bf16<<<NA4 / 256, 256>>>((const float4*)value, (uint2*)Ah, (uint2*)Al);
    split_bf16<<<NW4 / 256, 256>>>((const float4*)Wv, (uint2*)Wh, (uint2*)Wl);
    gemm_mma<<<mgrid, 256, GSMEM>>>(Ah, Al, Wh, Wl, bv, v_);

    dim3 agrid(S_ / QT, H_, B_ * C_);
    attn_tiled<<<agrid, 256, ATTN_SMEM>>>(attn);

    // Output projection
    split_bf16<<<NA4 / 256, 256>>>((const float4*)ctx_, (uint2*)Ah, (uint2*)Al);
    split_bf16<<<NW4 / 256, 256>>>((const float4*)Wo, (uint2*)Wh, (uint2*)Wl);
    gemm_mma<<<mgrid, 256, GSMEM>>>(Ah, Al, Wh, Wl, bo, out);
}